// round 15
// baseline (speedup 1.0000x reference)
#include <cuda_runtime.h>
#include <math.h>
#include <stdint.h>

#define TT 4096
#define HID 150
#define GAT 600
#define DIN 300

// ---------------- static device scratch (no allocation allowed) ----------------
__device__ float d_xg[4][TT][GAT];        // per-phase input projections  (39.3 MB)
__device__ float4 d_Wp[8 * 8 * 640 * 5];  // packed Whh: [s8][cta8][tid640][m5] (3.3 MB)
__device__ float d_out1[2][TT][2 * HID];  // layer-1 outputs
__device__ float d_HG[2][TT][2 * HID];    // layer-2 outputs: H=[0], G=[1]
__device__ float d_S[TT][TT];             // attention scores / softmax (64 MB)
__device__ float d_PQp[2][4][TT * 300];   // split-K partials for P/Q (39.3 MB)
__device__ float d_uvp[64][600];          // uvsum per-block partials
__device__ float d_inp[600];
__device__ float d_hid[2000];

// ---------------- PTX helpers ------------------------------------------------------
__device__ __forceinline__ uint32_t smem_u32(const void* p) {
    uint32_t a;
    asm("{ .reg .u64 t; cvta.to.shared.u64 t, %1; cvt.u32.u64 %0, t; }" : "=r"(a) : "l"(p));
    return a;
}
__device__ __forceinline__ uint32_t mapa_u32(uint32_t a, uint32_t rank) {
    uint32_t o;
    asm("mapa.shared::cluster.u32 %0, %1, %2;" : "=r"(o) : "r"(a), "r"(rank));
    return o;
}
__device__ __forceinline__ uint32_t ctarank() {
    uint32_t r;
    asm("mov.u32 %0, %%cluster_ctarank;" : "=r"(r));
    return r;
}
#define MBAR_INIT(m, cnt) \
    asm volatile("mbarrier.init.shared.b64 [%0], %1;" :: "r"(m), "r"(cnt) : "memory")
#define MBAR_EXPECT_TX(m, bytes) \
    asm volatile("mbarrier.arrive.expect_tx.shared.b64 _, [%0], %1;" :: "r"(m), "r"(bytes) : "memory")
#define ST_ASYNC_F32(raddr, val, rbar) \
    asm volatile("st.async.shared::cluster.mbarrier::complete_tx::bytes.b32 [%0], %1, [%2];" \
                 :: "r"(raddr), "r"(__float_as_uint(val)), "r"(rbar) : "memory")
#define MBAR_WAIT_PAR(m, par) do {                                                  \
    uint32_t _done = 0;                                                             \
    while (!_done) {                                                                \
        asm volatile("{\n\t.reg .pred P;\n\t"                                       \
            "mbarrier.try_wait.parity.acquire.cta.shared::cta.b64 P, [%1], %2, 0x989680;\n\t" \
            "selp.b32 %0, 1, 0, P;\n\t}"                                            \
            : "=r"(_done) : "r"(m), "r"(par) : "memory");                           \
    }                                                                               \
} while (0)
#define CLUSTER_SYNC() do {                                         \
    asm volatile("barrier.cluster.arrive.aligned;" ::: "memory");   \
    asm volatile("barrier.cluster.wait.aligned;" ::: "memory");     \
} while (0)

// packed f32x2 ops
#define FMA2(acc, a, b) asm("fma.rn.f32x2 %0, %1, %2, %0;" : "+l"(acc) : "l"(a), "l"(b))
#define ADD2(d, a, b)   asm("add.rn.f32x2 %0, %1, %2;" : "=l"(d) : "l"(a), "l"(b))
#define DUP2(dst, x)    asm("mov.b64 %0, {%1, %1};" : "=l"(dst) : "f"(x))
#define UNPK(lo, hi, v) asm("mov.b64 {%0, %1}, %2;" : "=f"(lo), "=f"(hi) : "l"(v))
#define LDS_V2U64(a, b, addr) \
    asm("ld.shared.v2.u64 {%0,%1},[%2];" : "=l"(a), "=l"(b) : "r"(addr))

// tf32 ops
#define CVT_TF32(u, f) asm("cvt.rna.tf32.f32 %0, %1;" : "=r"(u) : "f"(f))
#define MMA_TF32(d, a, b) \
    asm volatile("mma.sync.aligned.m16n8k8.row.col.f32.tf32.tf32.f32 " \
        "{%0,%1,%2,%3}, {%4,%5,%6,%7}, {%8,%9}, {%0,%1,%2,%3};" \
        : "+f"((d)[0]), "+f"((d)[1]), "+f"((d)[2]), "+f"((d)[3]) \
        : "r"((a)[0]), "r"((a)[1]), "r"((a)[2]), "r"((a)[3]), \
          "r"((b)[0]), "r"((b)[1]))

// MUFU.TANH-based gates (abs err ~5e-4, single MUFU each)
__device__ __forceinline__ float ftanh(float x) {
    float y; asm("tanh.approx.f32 %0, %1;" : "=f"(y) : "f"(x)); return y;
}
__device__ __forceinline__ float fsig(float x) { return fmaf(ftanh(0.5f * x), 0.5f, 0.5f); }

// convert a float4 to tf32 bit patterns stored as floats
__device__ __forceinline__ float4 cvt4_tf32(float4 v) {
    uint32_t a, b, c, d;
    CVT_TF32(a, v.x); CVT_TF32(b, v.y); CVT_TF32(c, v.z); CVT_TF32(d, v.w);
    float4 o;
    o.x = __uint_as_float(a); o.y = __uint_as_float(b);
    o.z = __uint_as_float(c); o.w = __uint_as_float(d);
    return o;
}

// ---------------- pack Whh for the 8-CTA split -------------------------------------
__global__ void pack_whh(const float* __restrict__ solvW, const float* __restrict__ soluW)
{
    int idx = blockIdx.x * 256 + threadIdx.x;
    const int total = 8 * 8 * 640 * 5;
    if (idx >= total) return;
    int m   = idx % 5;
    int tid = (idx / 5) % 640;
    int d   = (idx / 3200) % 8;
    int s8  = idx / 25600;
    int phase = s8 >> 2, s = s8 & 3, model = s >> 1, dir = s & 1;
    int ks = tid / 80, r = tid % 80;
    float4 v = {0.f, 0.f, 0.f, 0.f};
    if (r < 76) {
        int gt = r / 19, j = r % 19;
        int u = 19 * d + j;
        if (u < 150) {
            int o = gt * 150 + u;
            const float* W = (model ? soluW : solvW) + (size_t)(phase * 2 + dir) * GAT * HID
                             + (size_t)o * HID;
            int k0 = ks * 20 + m * 4;
            if (k0 + 0 < 150) v.x = W[k0 + 0];
            if (k0 + 1 < 150) v.y = W[k0 + 1];
            if (k0 + 2 < 150) v.z = W[k0 + 2];
            if (k0 + 3 < 150) v.w = W[k0 + 3];
        }
    }
    d_Wp[idx] = v;
}

// ---------------- LSTM recurrence: cluster of 8 CTAs per sequence ------------------
__global__ void __launch_bounds__(640, 1) lstm_rec_cl(int phase)
{
    int s = blockIdx.x >> 3;                 // sequence 0..3
    uint32_t d = ctarank();                  // 0..7
    int model = s >> 1, dir = s & 1;

    __shared__ __align__(16) float hs[2 * 160];     // double-buffered h (padded to 160)
    __shared__ __align__(16) float pbuf[960];       // partials: pbuf[r*12 + ks]
    __shared__ __align__(8) unsigned long long hbar;

    int tid = threadIdx.x;
    int ks = tid / 80;                       // k-octant 0..7
    int r  = tid % 80;                       // gate row within CTA slice
    const ulonglong2* Wb = reinterpret_cast<const ulonglong2*>(d_Wp)
                           + (size_t)((phase * 4 + s) * 8 + d) * 3200 + (size_t)tid * 5;
    uint64_t wlo[5], whi[5];
#pragma unroll
    for (int m = 0; m < 5; ++m) { ulonglong2 q = Wb[m]; wlo[m] = q.x; whi[m] = q.y; }

    if (tid < 2 * 160) hs[tid] = 0.f;
    uint32_t hbar_a = smem_u32(&hbar);
    uint32_t hs_a   = smem_u32(hs);
    if (tid == 0) MBAR_INIT(hbar_a, 1);
    __syncthreads();

    int u = 19 * (int)d + tid;
    bool upd = (tid < 19) && (u < 150);
    uint32_t rh[8], rb[8];
    if (upd) {
        for (uint32_t e = 0; e < 8; ++e) { rh[e] = mapa_u32(hs_a, e); rb[e] = mapa_u32(hbar_a, e); }
    }
    float c = 0.f;

    const float* xgb = &d_xg[s][0][0];
    float* outp = (phase == 0 ? &d_out1[model][0][0] : &d_HG[model][0][0]) + dir * HID;

    CLUSTER_SYNC();   // barriers + zeroed h visible cluster-wide

    float xv0 = 0.f, xv1 = 0.f, xv2 = 0.f, xv3 = 0.f;
    if (upd) {
        const float* xr = xgb + (size_t)(dir ? TT - 1 : 0) * GAT + u;
        xv0 = xr[0]; xv1 = xr[150]; xv2 = xr[300]; xv3 = xr[450];
    }
    const float4* p4 = reinterpret_cast<const float4*>(pbuf);

    for (int t = 0; t < TT; ++t) {
        int tt = dir ? (TT - 1 - t) : t;
        if (tid == 0) MBAR_EXPECT_TX(hbar_a, 150 * 4);

        float nx0 = 0.f, nx1 = 0.f, nx2 = 0.f, nx3 = 0.f;
        if (upd && (t + 1) < TT) {           // prefetch next step's xg a full step early
            int tn = dir ? (TT - 2 - t) : (t + 1);
            const float* xr = xgb + (size_t)tn * GAT + u;
            nx0 = xr[0]; nx1 = xr[150]; nx2 = xr[300]; nx3 = xr[450];
        }

        uint32_t hoff = hs_a + (uint32_t)((t & 1) * 640 + ks * 80);
        uint64_t aA = 0, aB = 0;
#pragma unroll
        for (int m = 0; m < 5; ++m) {
            uint64_t h0, h1;
            LDS_V2U64(h0, h1, hoff + m * 16);
            FMA2(aA, wlo[m], h0);
            FMA2(aB, whi[m], h1);
        }
        uint64_t aC; ADD2(aC, aA, aB);
        float plo, phi; UNPK(plo, phi, aC);
        pbuf[r * 12 + ks] = plo + phi;
        __syncthreads();

        if (upd) {
            int j = tid;
            float g[4];
#pragma unroll
            for (int gt = 0; gt < 4; ++gt) {
                int row = gt * 19 + j;
                float4 q0 = p4[row * 3], q1 = p4[row * 3 + 1];
                g[gt] = ((q0.x + q0.y) + (q0.z + q0.w)) + ((q1.x + q1.y) + (q1.z + q1.w));
            }
            float gi = fsig(g[0] + xv0), gf = fsig(g[1] + xv1);
            float gg = ftanh(g[2] + xv2), go = fsig(g[3] + xv3);
            c = gf * c + gi * gg;
            float hn = go * ftanh(c);
            uint32_t woff = (uint32_t)(((t + 1) & 1) * 640 + u * 4);
#pragma unroll
            for (int e = 0; e < 8; ++e) ST_ASYNC_F32(rh[e] + woff, hn, rb[e]);
            outp[(size_t)tt * (2 * HID) + u] = hn;
            xv0 = nx0; xv1 = nx1; xv2 = nx2; xv3 = nx3;
        }
        MBAR_WAIT_PAR(hbar_a, t & 1);        // all threads wait; cta-acquire orders h data
    }
    CLUSTER_SYNC();
}

// ---------------- shared staging helpers -------------------------------------------
// A staging: As[k][m], 128-wide M. B staging (64-wide): Bs[k][n].
template <int TATR, int TBTR>
struct Stage {
    static __device__ __forceinline__ float4 fetchA(
        const float* __restrict__ A, int lda, int M, int K, int mb, int kb, int tid, int e)
    {
        int aj = tid * 2 + e;
        float4 v = {0.f, 0.f, 0.f, 0.f};
        if (TATR == 0) {
            int m = mb + (aj >> 2), k = kb + (aj & 3) * 4;
            const float* p = A + (size_t)m * lda + k;
            if (m < M) {
                if (k + 3 < K) v = *(const float4*)p;
                else {
                    if (k + 0 < K) v.x = p[0];
                    if (k + 1 < K) v.y = p[1];
                    if (k + 2 < K) v.z = p[2];
                    if (k + 3 < K) v.w = p[3];
                }
            }
        } else {
            int k = kb + (aj >> 5), m = mb + (aj & 31) * 4;
            const float* p = A + (size_t)k * lda + m;
            if (k < K) {
                if (m + 3 < M) v = *(const float4*)p;
                else {
                    if (m + 0 < M) v.x = p[0];
                    if (m + 1 < M) v.y = p[1];
                    if (m + 2 < M) v.z = p[2];
                    if (m + 3 < M) v.w = p[3];
                }
            }
        }
        return v;
    }
    static __device__ __forceinline__ void storeA(float (*As)[16][132], int buf,
                                                  float4 v, int tid, int e)
    {
        int aj = tid * 2 + e;
        if (TATR == 0) {
            int m = aj >> 2, kq = aj & 3;
            As[buf][kq * 4 + 0][m] = v.x;
            As[buf][kq * 4 + 1][m] = v.y;
            As[buf][kq * 4 + 2][m] = v.z;
            As[buf][kq * 4 + 3][m] = v.w;
        } else {
            int k = aj >> 5, mq = aj & 31;
            *(float4*)&As[buf][k][mq * 4] = v;
        }
    }
    static __device__ __forceinline__ float4 fetchB(
        const float* __restrict__ B, int ldb, int N, int K, int nb, int kb, int tid)
    {
        float4 v = {0.f, 0.f, 0.f, 0.f};
        if (TBTR == 1) {
            int n = nb + (tid >> 2), k = kb + (tid & 3) * 4;
            const float* p = B + (size_t)n * ldb + k;
            if (n < N) {
                if (k + 3 < K) v = *(const float4*)p;
                else {
                    if (k + 0 < K) v.x = p[0];
                    if (k + 1 < K) v.y = p[1];
                    if (k + 2 < K) v.z = p[2];
                    if (k + 3 < K) v.w = p[3];
                }
            }
        } else {
            int k = kb + (tid >> 4), n = nb + (tid & 15) * 4;
            const float* p = B + (size_t)k * ldb + n;
            if (k < K) {
                if (n + 3 < N) v = *(const float4*)p;
                else {
                    if (n + 0 < N) v.x = p[0];
                    if (n + 1 < N) v.y = p[1];
                    if (n + 2 < N) v.z = p[2];
                    if (n + 3 < N) v.w = p[3];
                }
            }
        }
        return v;
    }
    static __device__ __forceinline__ void storeB(float (*Bs)[16][68], int buf,
                                                  float4 v, int tid)
    {
        if (TBTR == 1) {
            int n = tid >> 2, kq = tid & 3;
            Bs[buf][kq * 4 + 0][n] = v.x;
            Bs[buf][kq * 4 + 1][n] = v.y;
            Bs[buf][kq * 4 + 2][n] = v.z;
            Bs[buf][kq * 4 + 3][n] = v.w;
        } else {
            int k = tid >> 4, nq = tid & 15;
            *(float4*)&Bs[buf][k][nq * 4] = v;
        }
    }
    // 128-wide B staging (same index math as A, with N/TBTR semantics)
    static __device__ __forceinline__ float4 fetchB2(
        const float* __restrict__ B, int ldb, int N, int K, int nb, int kb, int tid, int e)
    {
        int aj = tid * 2 + e;
        float4 v = {0.f, 0.f, 0.f, 0.f};
        if (TBTR == 1) {
            int n = nb + (aj >> 2), k = kb + (aj & 3) * 4;
            const float* p = B + (size_t)n * ldb + k;
            if (n < N) {
                if (k + 3 < K) v = *(const float4*)p;
                else {
                    if (k + 0 < K) v.x = p[0];
                    if (k + 1 < K) v.y = p[1];
                    if (k + 2 < K) v.z = p[2];
                    if (k + 3 < K) v.w = p[3];
                }
            }
        } else {
            int k = kb + (aj >> 5), n = nb + (aj & 31) * 4;
            const float* p = B + (size_t)k * ldb + n;
            if (k < K) {
                if (n + 3 < N) v = *(const float4*)p;
                else {
                    if (n + 0 < N) v.x = p[0];
                    if (n + 1 < N) v.y = p[1];
                    if (n + 2 < N) v.z = p[2];
                    if (n + 3 < N) v.w = p[3];
                }
            }
        }
        return v;
    }
    static __device__ __forceinline__ void storeB2(float (*Bs)[16][132], int buf,
                                                   float4 v, int tid, int e)
    {
        int aj = tid * 2 + e;
        if (TBTR == 1) {
            int n = aj >> 2, kq = aj & 3;
            Bs[buf][kq * 4 + 0][n] = v.x;
            Bs[buf][kq * 4 + 1][n] = v.y;
            Bs[buf][kq * 4 + 2][n] = v.z;
            Bs[buf][kq * 4 + 3][n] = v.w;
        } else {
            int k = aj >> 5, nq = aj & 31;
            *(float4*)&Bs[buf][k][nq * 4] = v;
        }
    }
};

// ---------------- fp32 gemm128 (projection GEMM) -----------------------------------
template <int TATR, int TBTR, bool BIAS>
__device__ __forceinline__ void gemm128_body(
    float (*As)[16][132], float (*Bs)[16][68],
    const float* __restrict__ A, const float* __restrict__ B, float* __restrict__ C,
    const float* __restrict__ b1, const float* __restrict__ b2,
    int M, int N, int K, int lda, int ldb, int ldc, int nb, int mb)
{
    using St = Stage<TATR, TBTR>;
    int tid = threadIdx.x;
    int tn = tid & 15, tm = tid >> 4;
    uint32_t as_a = smem_u32(&As[0][0][0]);

    uint64_t acc[4][4];
#pragma unroll
    for (int i = 0; i < 4; i++)
#pragma unroll
        for (int j = 0; j < 4; j++) acc[i][j] = 0;

    float4 pa0 = St::fetchA(A, lda, M, K, mb, 0, tid, 0);
    float4 pa1 = St::fetchA(A, lda, M, K, mb, 0, tid, 1);
    float4 pb  = St::fetchB(B, ldb, N, K, nb, 0, tid);
    St::storeA(As, 0, pa0, tid, 0); St::storeA(As, 0, pa1, tid, 1);
    St::storeB(Bs, 0, pb, tid);
    __syncthreads();

    int nchunks = (K + 15) / 16;
    for (int ch = 0; ch < nchunks; ++ch) {
        int cur = ch & 1, nxt = cur ^ 1;
        bool more = (ch + 1) < nchunks;
        if (more) {
            int kbn = (ch + 1) * 16;
            pa0 = St::fetchA(A, lda, M, K, mb, kbn, tid, 0);
            pa1 = St::fetchA(A, lda, M, K, mb, kbn, tid, 1);
            pb  = St::fetchB(B, ldb, N, K, nb, kbn, tid);
        }
#pragma unroll
        for (int kk = 0; kk < 16; ++kk) {
            uint64_t a01, a23, a45, a67;
            uint32_t abase = as_a + (uint32_t)((cur * 16 * 132 + kk * 132 + tm * 8) * 4);
            LDS_V2U64(a01, a23, abase);
            LDS_V2U64(a45, a67, abase + 16);
            float4 bf = *(const float4*)&Bs[cur][kk][tn * 4];
            uint64_t bd;
            DUP2(bd, bf.x);
            FMA2(acc[0][0], a01, bd); FMA2(acc[1][0], a23, bd);
            FMA2(acc[2][0], a45, bd); FMA2(acc[3][0], a67, bd);
            DUP2(bd, bf.y);
            FMA2(acc[0][1], a01, bd); FMA2(acc[1][1], a23, bd);
            FMA2(acc[2][1], a45, bd); FMA2(acc[3][1], a67, bd);
            DUP2(bd, bf.z);
            FMA2(acc[0][2], a01, bd); FMA2(acc[1][2], a23, bd);
            FMA2(acc[2][2], a45, bd); FMA2(acc[3][2], a67, bd);
            DUP2(bd, bf.w);
            FMA2(acc[0][3], a01, bd); FMA2(acc[1][3], a23, bd);
            FMA2(acc[2][3], a45, bd); FMA2(acc[3][3], a67, bd);
        }
        if (more) {
            St::storeA(As, nxt, pa0, tid, 0); St::storeA(As, nxt, pa1, tid, 1);
            St::storeB(Bs, nxt, pb, tid);
        }
        __syncthreads();
    }

#pragma unroll
    for (int mp = 0; mp < 4; ++mp) {
        int r0 = mb + tm * 8 + mp * 2;
#pragma unroll
        for (int n = 0; n < 4; ++n) {
            int col = nb + tn * 4 + n;
            if (col >= N) continue;
            float lo, hi; UNPK(lo, hi, acc[mp][n]);
            float bb = 0.f;
            if (BIAS) bb = b1[col] + b2[col];
            if (r0 < M)     C[(size_t)r0 * ldc + col]       = lo + bb;
            if (r0 + 1 < M) C[(size_t)(r0 + 1) * ldc + col] = hi + bb;
        }
    }
}

// ---------------- tf32 tensor-core 128x128 GEMM body -------------------------------
// 8 warps as 4(m)x2(n); warp tile 32x64. Smem holds PRE-CONVERTED tf32 bit patterns
// (cvt.rna applied once at staging) so the mainloop issues no CVTs.
template <int TATR, int TBTR>
__device__ __forceinline__ void gemm_tf32_wide(
    float (*As)[16][132], float (*Bs)[16][132],
    const float* __restrict__ A, const float* __restrict__ B, float* __restrict__ C,
    int M, int N, int K, int lda, int ldb, int ldc, int nb, int mb)
{
    using St = Stage<TATR, TBTR>;
    int tid = threadIdx.x;
    int w = tid >> 5, lane = tid & 31;
    int wm = w >> 1, wn = w & 1;
    int g = lane >> 2, tig = lane & 3;

    float acc[2][8][4];
#pragma unroll
    for (int mi = 0; mi < 2; ++mi)
#pragma unroll
        for (int ni = 0; ni < 8; ++ni)
#pragma unroll
            for (int e = 0; e < 4; ++e) acc[mi][ni][e] = 0.f;

    float4 pa0 = cvt4_tf32(St::fetchA(A, lda, M, K, mb, 0, tid, 0));
    float4 pa1 = cvt4_tf32(St::fetchA(A, lda, M, K, mb, 0, tid, 1));
    float4 pb0 = cvt4_tf32(St::fetchB2(B, ldb, N, K, nb, 0, tid, 0));
    float4 pb1 = cvt4_tf32(St::fetchB2(B, ldb, N, K, nb, 0, tid, 1));
    St::storeA(As, 0, pa0, tid, 0); St::storeA(As, 0, pa1, tid, 1);
    St::storeB2(Bs, 0, pb0, tid, 0); St::storeB2(Bs, 0, pb1, tid, 1);
    __syncthreads();

    int nchunks = (K + 15) / 16;
    for (int ch = 0; ch < nchunks; ++ch) {
        int cur = ch & 1, nxt = cur ^ 1;
        bool more = (ch + 1) < nchunks;
        if (more) {
            int kbn = (ch + 1) * 16;
            pa0 = cvt4_tf32(St::fetchA(A, lda, M, K, mb, kbn, tid, 0));
            pa1 = cvt4_tf32(St::fetchA(A, lda, M, K, mb, kbn, tid, 1));
            pb0 = cvt4_tf32(St::fetchB2(B, ldb, N, K, nb, kbn, tid, 0));
            pb1 = cvt4_tf32(St::fetchB2(B, ldb, N, K, nb, kbn, tid, 1));
        }
#pragma unroll
        for (int ksv = 0; ksv < 16; ksv += 8) {
            uint32_t af[2][4];
#pragma unroll
            for (int mi = 0; mi < 2; ++mi) {
                int mrow = wm * 32 + mi * 16 + g;
                af[mi][0] = __float_as_uint(As[cur][ksv + tig][mrow]);
                af[mi][1] = __float_as_uint(As[cur][ksv + tig][mrow + 8]);
                af[mi][2] = __float_as_uint(As[cur][ksv + tig + 4][mrow]);
                af[mi][3] = __float_as_uint(As[cur][ksv + tig + 4][mrow + 8]);
            }
#pragma unroll
            for (int ni = 0; ni < 8; ++ni) {
                int ncol = wn * 64 + ni * 8 + g;
                uint32_t bf[2];
                bf[0] = __float_as_uint(Bs[cur][ksv + tig][ncol]);
                bf[1] = __float_as_uint(Bs[cur][ksv + tig + 4][ncol]);
                MMA_TF32(acc[0][ni], af[0], bf);
                MMA_TF32(acc[1][ni], af[1], bf);
            }
        }
        if (more) {
            St::storeA(As, nxt, pa0, tid, 0); St::storeA(As, nxt, pa1, tid, 1);
            St::storeB2(Bs, nxt, pb0, tid, 0); St::storeB2(Bs, nxt, pb1, tid, 1);
        }
        __syncthreads();
    }

#pragma unroll
    for (int mi = 0; mi < 2; ++mi) {
        int row0 = mb + wm * 32 + mi * 16 + g;
#pragma unroll
        for (int ni = 0; ni < 8; ++ni) {
            int col0 = nb + wn * 64 + ni * 8 + tig * 2;
            if (col0 < N)     C[(size_t)row0 * ldc + col0]           = acc[mi][ni][0];
            if (col0 + 1 < N) C[(size_t)row0 * ldc + col0 + 1]       = acc[mi][ni][1];
            if (col0 < N)     C[(size_t)(row0 + 8) * ldc + col0]     = acc[mi][ni][2];
            if (col0 + 1 < N) C[(size_t)(row0 + 8) * ldc + col0 + 1] = acc[mi][ni][3];
        }
    }
}

// ---------------- all 4 per-phase projection GEMMs in ONE launch (grid.z = s) ------
__global__ void __launch_bounds__(256, 2) gemm_proj(
    int phase,
    const float* __restrict__ in_solv, const float* __restrict__ in_solu,
    const float* __restrict__ solv_Wih, const float* __restrict__ solu_Wih,
    const float* __restrict__ solv_bih, const float* __restrict__ solv_bhh,
    const float* __restrict__ solu_bih, const float* __restrict__ solu_bhh)
{
    __shared__ __align__(16) float As[2][16][132];
    __shared__ __align__(16) float Bs[2][16][68];
    int s = blockIdx.z, model = s >> 1, dir = s & 1;
    const float* X = (phase == 0) ? (model ? in_solu : in_solv) : &d_out1[model][0][0];
    const float* W  = (model ? solu_Wih : solv_Wih) + (size_t)(phase * 2 + dir) * GAT * DIN;
    const float* B1 = (model ? solu_bih : solv_bih) + (size_t)(phase * 2 + dir) * GAT;
    const float* B2 = (model ? solu_bhh : solv_bhh) + (size_t)(phase * 2 + dir) * GAT;
    gemm128_body<0, 1, true>(As, Bs, X, W, &d_xg[s][0][0], B1, B2,
                             TT, GAT, DIN, DIN, DIN, GAT,
                             blockIdx.x * 64, blockIdx.y * 128);
}

// ---------------- S = H @ G^T (tf32, 128x128 tiles) --------------------------------
__global__ void __launch_bounds__(256, 2) gemm_s_tf32(
    const float* __restrict__ H, const float* __restrict__ G, float* __restrict__ S)
{
    __shared__ __align__(16) float As[2][16][132];
    __shared__ __align__(16) float Bs[2][16][132];
    gemm_tf32_wide<0, 1>(As, Bs, H, G, S, TT, TT, 300, 300, 300, TT,
                         blockIdx.x * 128, blockIdx.y * 128);
}

// ---------------- split-K P/Q partials (tf32 128x128), grid.z = (chunk<<1)|pq ------
__global__ void __launch_bounds__(256, 2) gemm_pq_split(
    const float* __restrict__ S, const float* __restrict__ G, const float* __restrict__ H)
{
    __shared__ __align__(16) float As[2][16][132];
    __shared__ __align__(16) float Bs[2][16][132];
    int pq = blockIdx.z & 1, c = blockIdx.z >> 1;
    float* Cout = &d_PQp[pq][c][0];
    if (pq == 0) {
        gemm_tf32_wide<0, 0>(As, Bs, S + (size_t)c * 1024,
                             G + (size_t)c * 1024 * 300, Cout,
                             TT, 300, 1024, TT, 300, 300,
                             blockIdx.x * 128, blockIdx.y * 128);
    } else {
        gemm_tf32_wide<1, 0>(As, Bs, S + (size_t)c * 1024 * TT,
                             H + (size_t)c * 1024 * 300, Cout,
                             TT, 300, 1024, TT, 300, 300,
                             blockIdx.x * 128, blockIdx.y * 128);
    }
}

// ---------------- row softmax of d_S in place (shfl reductions) --------------------
__global__ void __launch_bounds__(256) softmax_rows()
{
    int row = blockIdx.x;
    float* r = &d_S[row][0];
    int tid = threadIdx.x;
    int lane = tid & 31, wid = tid >> 5;
    __shared__ float red[8];
    __shared__ float bc;

    float v[16];
#pragma unroll
    for (int i = 0; i < 16; i++) v[i] = r[tid + i * 256];

    float m = -1e30f;
#pragma unroll
    for (int i = 0; i < 16; i++) m = fmaxf(m, v[i]);
#pragma unroll
    for (int o = 16; o; o >>= 1) m = fmaxf(m, __shfl_xor_sync(0xffffffffu, m, o));
    if (lane == 0) red[wid] = m;
    __syncthreads();
    if (tid == 0) {
        float mm = red[0];
#pragma unroll
        for (int i = 1; i < 8; i++) mm = fmaxf(mm, red[i]);
        bc = mm;
    }
    __syncthreads();
    m = bc;

    float ssum = 0.f;
#pragma unroll
    for (int i = 0; i < 16; i++) { v[i] = __expf(v[i] - m); ssum += v[i]; }
#pragma unroll
    for (int o = 16; o; o >>= 1) ssum += __shfl_xor_sync(0xffffffffu, ssum, o);
    if (lane == 0) red[wid] = ssum;
    __syncthreads();
    if (tid == 0) {
        float ss = red[0];
#pragma unroll
        for (int i = 1; i < 8; i++) ss += red[i];
        bc = 1.f / ss;
    }
    __syncthreads();
    float inv = bc;

#pragma unroll
    for (int i = 0; i < 16; i++) r[tid + i * 256] = v[i] * inv;
}

// ---------------- u/v sums (reads split-K partials directly, coalesced) ------------
__global__ void __launch_bounds__(256) uvsum_part()
{
    int b = blockIdx.x, tid = threadIdx.x;
    const float* H  = &d_HG[0][0][0];
    const float* G  = &d_HG[1][0][0];
    const float* P0 = &d_PQp[0][0][0], *P1 = &d_PQp[0][1][0];
    const float* P2 = &d_PQp[0][2][0], *P3 = &d_PQp[0][3][0];
    const float* Q0 = &d_PQp[1][0][0], *Q1 = &d_PQp[1][1][0];
    const float* Q2 = &d_PQp[1][2][0], *Q3 = &d_PQp[1][3][0];

    float a0 = 0.f, a1 = 0.f, a2 = 0.f;
    for (int i = b * 64; i < b * 64 + 64; ++i) {
        size_t base = (size_t)i * 300;
        {
            size_t o = base + tid;
            float p = (P0[o] + P1[o]) + (P2[o] + P3[o]);
            a0 += fmaxf(H[o], p);
        }
        {
            int d = tid + 256;
            if (d < 300) {
                size_t o = base + d;
                float p = (P0[o] + P1[o]) + (P2[o] + P3[o]);
                a1 += fmaxf(H[o], p);
            } else {
                size_t o = base + (d - 300);
                float q = (Q0[o] + Q1[o]) + (Q2[o] + Q3[o]);
                a1 += fmaxf(G[o], q);
            }
        }
        if (tid < 88) {
            size_t o = base + tid + 212;
            float q = (Q0[o] + Q1[o]) + (Q2[o] + Q3[o]);
            a2 += fmaxf(G[o], q);
        }
    }
    d_uvp[b][tid] = a0;
    d_uvp[b][tid + 256] = a1;
    if (tid < 88) d_uvp[b][tid + 512] = a2;
}

__global__ void __launch_bounds__(256) uvsum_final()
{
    int d = blockIdx.x * 256 + threadIdx.x;
    if (d >= 600) return;
    float s = 0.f;
#pragma unroll
    for (int b = 0; b < 64; ++b) s += d_uvp[b][d];
    d_inp[d] = s;
}

// ---------------- FC head ----------------------------------------------------------
__global__ void fc1_kernel(const float* __restrict__ w, const float* __restrict__ b)
{
    __shared__ float inp[600];
    int tid = threadIdx.x;
    for (int k = tid; k < 600; k += 128) inp[k] = d_inp[k];
    __syncthreads();
    int o = blockIdx.x * 128 + tid;
    if (o < 2000) {
        const float* wr = w + (size_t)o * 600;
        float s = b[o];
        for (int k = 0; k < 600; k++) s += wr[k] * inp[k];
        d_hid[o] = fmaxf(s, 0.f);
    }
}

__global__ void fc2_kernel(const float* __restrict__ w, const float* __restrict__ b,
                           float* __restrict__ out)
{
    int tid = threadIdx.x;
    float s = 0.f;
    for (int k = tid; k < 2000; k += 256) s += d_hid[k] * w[k];
    __shared__ float red[256];
    red[tid] = s; __syncthreads();
    for (int st = 128; st; st >>= 1) { if (tid < st) red[tid] += red[tid + st]; __syncthreads(); }
    if (tid == 0) out[0] = red[0] + b[0];
}

// ---------------- launch orchestration ---------------------------------------------
extern "C" void kernel_launch(void* const* d_in, const int* in_sizes, int n_in,
                              void* d_out, int out_size)
{
    const float* in_solv  = (const float*)d_in[0];
    const float* in_solu  = (const float*)d_in[1];
    const float* solv_Wih = (const float*)d_in[2];
    const float* solv_Whh = (const float*)d_in[3];
    const float* solv_bih = (const float*)d_in[4];
    const float* solv_bhh = (const float*)d_in[5];
    const float* solu_Wih = (const float*)d_in[6];
    const float* solu_Whh = (const float*)d_in[7];
    const float* solu_bih = (const float*)d_in[8];
    const float* solu_bhh = (const float*)d_in[9];
    const float* fc1_w    = (const float*)d_in[10];
    const float* fc1_b    = (const float*)d_in[11];
    const float* fc2_w    = (const float*)d_in[12];
    const float* fc2_b    = (const float*)d_in[13];

    float *p_HG, *p_S;
    cudaGetSymbolAddress((void**)&p_HG, d_HG);
    cudaGetSymbolAddress((void**)&p_S,  d_S);

    pack_whh<<<(8 * 8 * 640 * 5 + 255) / 256, 256>>>(solv_Whh, solu_Whh);

    for (int phase = 0; phase < 2; ++phase) {
        gemm_proj<<<dim3(10, 32, 4), 256>>>(phase, in_solv, in_solu,
                                            solv_Wih, solu_Wih,
                                            solv_bih, solv_bhh, solu_bih, solu_bhh);
        cudaLaunchConfig_t cfg = {};
        cfg.gridDim = dim3(32, 1, 1);
        cfg.blockDim = dim3(640, 1, 1);
        cfg.dynamicSmemBytes = 0;
        cfg.stream = 0;
        cudaLaunchAttribute attrs[1];
        attrs[0].id = cudaLaunchAttributeClusterDimension;
        attrs[0].val.clusterDim = {8, 1, 1};
        cfg.attrs = attrs;
        cfg.numAttrs = 1;
        cudaLaunchKernelEx(&cfg, lstm_rec_cl, phase);
    }

    const float* H = p_HG;
    const float* G = p_HG + (size_t)TT * 300;

    gemm_s_tf32<<<dim3(32, 32), 256>>>(H, G, p_S);
    softmax_rows<<<TT, 256>>>();
    gemm_pq_split<<<dim3(3, 32, 8), 256>>>(p_S, G, H);
    uvsum_part<<<64, 256>>>();
    uvsum_final<<<3, 256>>>();
    fc1_kernel<<<(2000 + 127) / 128, 128>>>(fc1_w, fc1_b);
    fc2_kernel<<<1, 256>>>(fc2_w, fc2_b, (float*)d_out);
}

// round 16
// speedup vs baseline: 1.4907x; 1.4907x over previous
#include <cuda_runtime.h>
#include <math.h>
#include <stdint.h>

#define TT 4096
#define HID 150
#define GAT 600
#define DIN 300

// ---------------- static device scratch (no allocation allowed) ----------------
__device__ float d_xg[4][TT][GAT];        // per-phase input projections  (39.3 MB)
__device__ float4 d_Wp[8 * 8 * 640 * 5];  // packed Whh: [s8][cta8][tid640][m5] (3.3 MB)
__device__ float d_out1[2][TT][2 * HID];  // layer-1 outputs
__device__ float d_HG[2][TT][2 * HID];    // layer-2 outputs: H=[0], G=[1]
__device__ float d_S[TT][TT];             // attention scores / softmax (64 MB)
__device__ float d_PQp[2][4][TT * 300];   // split-K partials for P/Q (39.3 MB)
__device__ float d_uvp[64][600];          // uvsum per-block partials
__device__ float d_inp[600];
__device__ float d_hid[2000];

// ---------------- PTX helpers ------------------------------------------------------
__device__ __forceinline__ uint32_t smem_u32(const void* p) {
    uint32_t a;
    asm("{ .reg .u64 t; cvta.to.shared.u64 t, %1; cvt.u32.u64 %0, t; }" : "=r"(a) : "l"(p));
    return a;
}
__device__ __forceinline__ uint32_t mapa_u32(uint32_t a, uint32_t rank) {
    uint32_t o;
    asm("mapa.shared::cluster.u32 %0, %1, %2;" : "=r"(o) : "r"(a), "r"(rank));
    return o;
}
__device__ __forceinline__ uint32_t ctarank() {
    uint32_t r;
    asm("mov.u32 %0, %%cluster_ctarank;" : "=r"(r));
    return r;
}
#define MBAR_INIT(m, cnt) \
    asm volatile("mbarrier.init.shared.b64 [%0], %1;" :: "r"(m), "r"(cnt) : "memory")
#define MBAR_EXPECT_TX(m, bytes) \
    asm volatile("mbarrier.arrive.expect_tx.shared.b64 _, [%0], %1;" :: "r"(m), "r"(bytes) : "memory")
#define ST_ASYNC_F32(raddr, val, rbar) \
    asm volatile("st.async.shared::cluster.mbarrier::complete_tx::bytes.b32 [%0], %1, [%2];" \
                 :: "r"(raddr), "r"(__float_as_uint(val)), "r"(rbar) : "memory")
#define MBAR_WAIT_PAR(m, par) do {                                                  \
    uint32_t _done = 0;                                                             \
    while (!_done) {                                                                \
        asm volatile("{\n\t.reg .pred P;\n\t"                                       \
            "mbarrier.try_wait.parity.acquire.cta.shared::cta.b64 P, [%1], %2, 0x989680;\n\t" \
            "selp.b32 %0, 1, 0, P;\n\t}"                                            \
            : "=r"(_done) : "r"(m), "r"(par) : "memory");                           \
    }                                                                               \
} while (0)
#define CLUSTER_SYNC() do {                                         \
    asm volatile("barrier.cluster.arrive.aligned;" ::: "memory");   \
    asm volatile("barrier.cluster.wait.aligned;" ::: "memory");     \
} while (0)

// packed f32x2 ops
#define FMA2(acc, a, b) asm("fma.rn.f32x2 %0, %1, %2, %0;" : "+l"(acc) : "l"(a), "l"(b))
#define ADD2(d, a, b)   asm("add.rn.f32x2 %0, %1, %2;" : "=l"(d) : "l"(a), "l"(b))
#define DUP2(dst, x)    asm("mov.b64 %0, {%1, %1};" : "=l"(dst) : "f"(x))
#define UNPK(lo, hi, v) asm("mov.b64 {%0, %1}, %2;" : "=f"(lo), "=f"(hi) : "l"(v))
#define LDS_V2U64(a, b, addr) \
    asm("ld.shared.v2.u64 {%0,%1},[%2];" : "=l"(a), "=l"(b) : "r"(addr))

// tf32 ops
#define CVT_TF32(u, f) asm("cvt.rna.tf32.f32 %0, %1;" : "=r"(u) : "f"(f))
#define MMA_TF32(d, a, b) \
    asm volatile("mma.sync.aligned.m16n8k8.row.col.f32.tf32.tf32.f32 " \
        "{%0,%1,%2,%3}, {%4,%5,%6,%7}, {%8,%9}, {%0,%1,%2,%3};" \
        : "+f"((d)[0]), "+f"((d)[1]), "+f"((d)[2]), "+f"((d)[3]) \
        : "r"((a)[0]), "r"((a)[1]), "r"((a)[2]), "r"((a)[3]), \
          "r"((b)[0]), "r"((b)[1]))

// MUFU.TANH-based gates (abs err ~5e-4, single MUFU each)
__device__ __forceinline__ float ftanh(float x) {
    float y; asm("tanh.approx.f32 %0, %1;" : "=f"(y) : "f"(x)); return y;
}
__device__ __forceinline__ float fsig(float x) { return fmaf(ftanh(0.5f * x), 0.5f, 0.5f); }

// ---------------- pack Whh for the 8-CTA split -------------------------------------
__global__ void pack_whh(const float* __restrict__ solvW, const float* __restrict__ soluW)
{
    int idx = blockIdx.x * 256 + threadIdx.x;
    const int total = 8 * 8 * 640 * 5;
    if (idx >= total) return;
    int m   = idx % 5;
    int tid = (idx / 5) % 640;
    int d   = (idx / 3200) % 8;
    int s8  = idx / 25600;
    int phase = s8 >> 2, s = s8 & 3, model = s >> 1, dir = s & 1;
    int ks = tid / 80, r = tid % 80;
    float4 v = {0.f, 0.f, 0.f, 0.f};
    if (r < 76) {
        int gt = r / 19, j = r % 19;
        int u = 19 * d + j;
        if (u < 150) {
            int o = gt * 150 + u;
            const float* W = (model ? soluW : solvW) + (size_t)(phase * 2 + dir) * GAT * HID
                             + (size_t)o * HID;
            int k0 = ks * 20 + m * 4;
            if (k0 + 0 < 150) v.x = W[k0 + 0];
            if (k0 + 1 < 150) v.y = W[k0 + 1];
            if (k0 + 2 < 150) v.z = W[k0 + 2];
            if (k0 + 3 < 150) v.w = W[k0 + 3];
        }
    }
    d_Wp[idx] = v;
}

// ---------------- LSTM recurrence: cluster of 8 CTAs per sequence ------------------
__global__ void __launch_bounds__(640, 1) lstm_rec_cl(int phase)
{
    int s = blockIdx.x >> 3;                 // sequence 0..3
    uint32_t d = ctarank();                  // 0..7
    int model = s >> 1, dir = s & 1;

    __shared__ __align__(16) float hs[2 * 160];     // double-buffered h (padded to 160)
    __shared__ __align__(16) float pbuf[960];       // partials: pbuf[r*12 + ks]
    __shared__ __align__(8) unsigned long long hbar;

    int tid = threadIdx.x;
    int ks = tid / 80;                       // k-octant 0..7
    int r  = tid % 80;                       // gate row within CTA slice
    const ulonglong2* Wb = reinterpret_cast<const ulonglong2*>(d_Wp)
                           + (size_t)((phase * 4 + s) * 8 + d) * 3200 + (size_t)tid * 5;
    uint64_t wlo[5], whi[5];
#pragma unroll
    for (int m = 0; m < 5; ++m) { ulonglong2 q = Wb[m]; wlo[m] = q.x; whi[m] = q.y; }

    if (tid < 2 * 160) hs[tid] = 0.f;
    uint32_t hbar_a = smem_u32(&hbar);
    uint32_t hs_a   = smem_u32(hs);
    if (tid == 0) MBAR_INIT(hbar_a, 1);
    __syncthreads();

    int u = 19 * (int)d + tid;
    bool upd = (tid < 19) && (u < 150);
    uint32_t rh[8], rb[8];
    if (upd) {
        for (uint32_t e = 0; e < 8; ++e) { rh[e] = mapa_u32(hs_a, e); rb[e] = mapa_u32(hbar_a, e); }
    }
    float c = 0.f;

    const float* xgb = &d_xg[s][0][0];
    float* outp = (phase == 0 ? &d_out1[model][0][0] : &d_HG[model][0][0]) + dir * HID;

    CLUSTER_SYNC();   // barriers + zeroed h visible cluster-wide

    float xv0 = 0.f, xv1 = 0.f, xv2 = 0.f, xv3 = 0.f;
    if (upd) {
        const float* xr = xgb + (size_t)(dir ? TT - 1 : 0) * GAT + u;
        xv0 = xr[0]; xv1 = xr[150]; xv2 = xr[300]; xv3 = xr[450];
    }
    const float4* p4 = reinterpret_cast<const float4*>(pbuf);

    for (int t = 0; t < TT; ++t) {
        int tt = dir ? (TT - 1 - t) : t;
        if (tid == 0) MBAR_EXPECT_TX(hbar_a, 150 * 4);

        float nx0 = 0.f, nx1 = 0.f, nx2 = 0.f, nx3 = 0.f;
        if (upd && (t + 1) < TT) {           // prefetch next step's xg a full step early
            int tn = dir ? (TT - 2 - t) : (t + 1);
            const float* xr = xgb + (size_t)tn * GAT + u;
            nx0 = xr[0]; nx1 = xr[150]; nx2 = xr[300]; nx3 = xr[450];
        }

        uint32_t hoff = hs_a + (uint32_t)((t & 1) * 640 + ks * 80);
        uint64_t aA = 0, aB = 0;
#pragma unroll
        for (int m = 0; m < 5; ++m) {
            uint64_t h0, h1;
            LDS_V2U64(h0, h1, hoff + m * 16);
            FMA2(aA, wlo[m], h0);
            FMA2(aB, whi[m], h1);
        }
        uint64_t aC; ADD2(aC, aA, aB);
        float plo, phi; UNPK(plo, phi, aC);
        pbuf[r * 12 + ks] = plo + phi;
        __syncthreads();

        if (upd) {
            int j = tid;
            float g[4];
#pragma unroll
            for (int gt = 0; gt < 4; ++gt) {
                int row = gt * 19 + j;
                float4 q0 = p4[row * 3], q1 = p4[row * 3 + 1];
                g[gt] = ((q0.x + q0.y) + (q0.z + q0.w)) + ((q1.x + q1.y) + (q1.z + q1.w));
            }
            float gi = fsig(g[0] + xv0), gf = fsig(g[1] + xv1);
            float gg = ftanh(g[2] + xv2), go = fsig(g[3] + xv3);
            c = gf * c + gi * gg;
            float hn = go * ftanh(c);
            uint32_t woff = (uint32_t)(((t + 1) & 1) * 640 + u * 4);
#pragma unroll
            for (int e = 0; e < 8; ++e) ST_ASYNC_F32(rh[e] + woff, hn, rb[e]);
            outp[(size_t)tt * (2 * HID) + u] = hn;
            xv0 = nx0; xv1 = nx1; xv2 = nx2; xv3 = nx3;
        }
        MBAR_WAIT_PAR(hbar_a, t & 1);        // all threads wait; cta-acquire orders h data
    }
    CLUSTER_SYNC();
}

// ---------------- shared staging helpers -------------------------------------------
// A staging: As[k][m], 128-wide M. B staging (64-wide): Bs[k][n].
template <int TATR, int TBTR>
struct Stage {
    static __device__ __forceinline__ float4 fetchA(
        const float* __restrict__ A, int lda, int M, int K, int mb, int kb, int tid, int e)
    {
        int aj = tid * 2 + e;
        float4 v = {0.f, 0.f, 0.f, 0.f};
        if (TATR == 0) {
            int m = mb + (aj >> 2), k = kb + (aj & 3) * 4;
            const float* p = A + (size_t)m * lda + k;
            if (m < M) {
                if (k + 3 < K) v = *(const float4*)p;
                else {
                    if (k + 0 < K) v.x = p[0];
                    if (k + 1 < K) v.y = p[1];
                    if (k + 2 < K) v.z = p[2];
                    if (k + 3 < K) v.w = p[3];
                }
            }
        } else {
            int k = kb + (aj >> 5), m = mb + (aj & 31) * 4;
            const float* p = A + (size_t)k * lda + m;
            if (k < K) {
                if (m + 3 < M) v = *(const float4*)p;
                else {
                    if (m + 0 < M) v.x = p[0];
                    if (m + 1 < M) v.y = p[1];
                    if (m + 2 < M) v.z = p[2];
                    if (m + 3 < M) v.w = p[3];
                }
            }
        }
        return v;
    }
    static __device__ __forceinline__ void storeA(float (*As)[16][132], int buf,
                                                  float4 v, int tid, int e)
    {
        int aj = tid * 2 + e;
        if (TATR == 0) {
            int m = aj >> 2, kq = aj & 3;
            As[buf][kq * 4 + 0][m] = v.x;
            As[buf][kq * 4 + 1][m] = v.y;
            As[buf][kq * 4 + 2][m] = v.z;
            As[buf][kq * 4 + 3][m] = v.w;
        } else {
            int k = aj >> 5, mq = aj & 31;
            *(float4*)&As[buf][k][mq * 4] = v;
        }
    }
    static __device__ __forceinline__ float4 fetchB(
        const float* __restrict__ B, int ldb, int N, int K, int nb, int kb, int tid)
    {
        float4 v = {0.f, 0.f, 0.f, 0.f};
        if (TBTR == 1) {
            int n = nb + (tid >> 2), k = kb + (tid & 3) * 4;
            const float* p = B + (size_t)n * ldb + k;
            if (n < N) {
                if (k + 3 < K) v = *(const float4*)p;
                else {
                    if (k + 0 < K) v.x = p[0];
                    if (k + 1 < K) v.y = p[1];
                    if (k + 2 < K) v.z = p[2];
                    if (k + 3 < K) v.w = p[3];
                }
            }
        } else {
            int k = kb + (tid >> 4), n = nb + (tid & 15) * 4;
            const float* p = B + (size_t)k * ldb + n;
            if (k < K) {
                if (n + 3 < N) v = *(const float4*)p;
                else {
                    if (n + 0 < N) v.x = p[0];
                    if (n + 1 < N) v.y = p[1];
                    if (n + 2 < N) v.z = p[2];
                    if (n + 3 < N) v.w = p[3];
                }
            }
        }
        return v;
    }
    static __device__ __forceinline__ void storeB(float (*Bs)[16][68], int buf,
                                                  float4 v, int tid)
    {
        if (TBTR == 1) {
            int n = tid >> 2, kq = tid & 3;
            Bs[buf][kq * 4 + 0][n] = v.x;
            Bs[buf][kq * 4 + 1][n] = v.y;
            Bs[buf][kq * 4 + 2][n] = v.z;
            Bs[buf][kq * 4 + 3][n] = v.w;
        } else {
            int k = tid >> 4, nq = tid & 15;
            *(float4*)&Bs[buf][k][nq * 4] = v;
        }
    }
    // 128-wide B staging (same index math as A, with N/TBTR semantics)
    static __device__ __forceinline__ float4 fetchB2(
        const float* __restrict__ B, int ldb, int N, int K, int nb, int kb, int tid, int e)
    {
        int aj = tid * 2 + e;
        float4 v = {0.f, 0.f, 0.f, 0.f};
        if (TBTR == 1) {
            int n = nb + (aj >> 2), k = kb + (aj & 3) * 4;
            const float* p = B + (size_t)n * ldb + k;
            if (n < N) {
                if (k + 3 < K) v = *(const float4*)p;
                else {
                    if (k + 0 < K) v.x = p[0];
                    if (k + 1 < K) v.y = p[1];
                    if (k + 2 < K) v.z = p[2];
                    if (k + 3 < K) v.w = p[3];
                }
            }
        } else {
            int k = kb + (aj >> 5), n = nb + (aj & 31) * 4;
            const float* p = B + (size_t)k * ldb + n;
            if (k < K) {
                if (n + 3 < N) v = *(const float4*)p;
                else {
                    if (n + 0 < N) v.x = p[0];
                    if (n + 1 < N) v.y = p[1];
                    if (n + 2 < N) v.z = p[2];
                    if (n + 3 < N) v.w = p[3];
                }
            }
        }
        return v;
    }
    static __device__ __forceinline__ void storeB2(float (*Bs)[16][132], int buf,
                                                   float4 v, int tid, int e)
    {
        int aj = tid * 2 + e;
        if (TBTR == 1) {
            int n = aj >> 2, kq = aj & 3;
            Bs[buf][kq * 4 + 0][n] = v.x;
            Bs[buf][kq * 4 + 1][n] = v.y;
            Bs[buf][kq * 4 + 2][n] = v.z;
            Bs[buf][kq * 4 + 3][n] = v.w;
        } else {
            int k = aj >> 5, nq = aj & 31;
            *(float4*)&Bs[buf][k][nq * 4] = v;
        }
    }
};

// ---------------- fp32 gemm128 (projection GEMM) -----------------------------------
template <int TATR, int TBTR, bool BIAS>
__device__ __forceinline__ void gemm128_body(
    float (*As)[16][132], float (*Bs)[16][68],
    const float* __restrict__ A, const float* __restrict__ B, float* __restrict__ C,
    const float* __restrict__ b1, const float* __restrict__ b2,
    int M, int N, int K, int lda, int ldb, int ldc, int nb, int mb)
{
    using St = Stage<TATR, TBTR>;
    int tid = threadIdx.x;
    int tn = tid & 15, tm = tid >> 4;
    uint32_t as_a = smem_u32(&As[0][0][0]);

    uint64_t acc[4][4];
#pragma unroll
    for (int i = 0; i < 4; i++)
#pragma unroll
        for (int j = 0; j < 4; j++) acc[i][j] = 0;

    float4 pa0 = St::fetchA(A, lda, M, K, mb, 0, tid, 0);
    float4 pa1 = St::fetchA(A, lda, M, K, mb, 0, tid, 1);
    float4 pb  = St::fetchB(B, ldb, N, K, nb, 0, tid);
    St::storeA(As, 0, pa0, tid, 0); St::storeA(As, 0, pa1, tid, 1);
    St::storeB(Bs, 0, pb, tid);
    __syncthreads();

    int nchunks = (K + 15) / 16;
    for (int ch = 0; ch < nchunks; ++ch) {
        int cur = ch & 1, nxt = cur ^ 1;
        bool more = (ch + 1) < nchunks;
        if (more) {
            int kbn = (ch + 1) * 16;
            pa0 = St::fetchA(A, lda, M, K, mb, kbn, tid, 0);
            pa1 = St::fetchA(A, lda, M, K, mb, kbn, tid, 1);
            pb  = St::fetchB(B, ldb, N, K, nb, kbn, tid);
        }
#pragma unroll
        for (int kk = 0; kk < 16; ++kk) {
            uint64_t a01, a23, a45, a67;
            uint32_t abase = as_a + (uint32_t)((cur * 16 * 132 + kk * 132 + tm * 8) * 4);
            LDS_V2U64(a01, a23, abase);
            LDS_V2U64(a45, a67, abase + 16);
            float4 bf = *(const float4*)&Bs[cur][kk][tn * 4];
            uint64_t bd;
            DUP2(bd, bf.x);
            FMA2(acc[0][0], a01, bd); FMA2(acc[1][0], a23, bd);
            FMA2(acc[2][0], a45, bd); FMA2(acc[3][0], a67, bd);
            DUP2(bd, bf.y);
            FMA2(acc[0][1], a01, bd); FMA2(acc[1][1], a23, bd);
            FMA2(acc[2][1], a45, bd); FMA2(acc[3][1], a67, bd);
            DUP2(bd, bf.z);
            FMA2(acc[0][2], a01, bd); FMA2(acc[1][2], a23, bd);
            FMA2(acc[2][2], a45, bd); FMA2(acc[3][2], a67, bd);
            DUP2(bd, bf.w);
            FMA2(acc[0][3], a01, bd); FMA2(acc[1][3], a23, bd);
            FMA2(acc[2][3], a45, bd); FMA2(acc[3][3], a67, bd);
        }
        if (more) {
            St::storeA(As, nxt, pa0, tid, 0); St::storeA(As, nxt, pa1, tid, 1);
            St::storeB(Bs, nxt, pb, tid);
        }
        __syncthreads();
    }

#pragma unroll
    for (int mp = 0; mp < 4; ++mp) {
        int r0 = mb + tm * 8 + mp * 2;
#pragma unroll
        for (int n = 0; n < 4; ++n) {
            int col = nb + tn * 4 + n;
            if (col >= N) continue;
            float lo, hi; UNPK(lo, hi, acc[mp][n]);
            float bb = 0.f;
            if (BIAS) bb = b1[col] + b2[col];
            if (r0 < M)     C[(size_t)r0 * ldc + col]       = lo + bb;
            if (r0 + 1 < M) C[(size_t)(r0 + 1) * ldc + col] = hi + bb;
        }
    }
}

// ---------------- tf32 tensor-core 128x128 GEMM body -------------------------------
// 8 warps as 4(m)x2(n); warp tile 32x64; mma.m16n8k8 tf32. M must be 128-aligned.
template <int TATR, int TBTR>
__device__ __forceinline__ void gemm_tf32_wide(
    float (*As)[16][132], float (*Bs)[16][132],
    const float* __restrict__ A, const float* __restrict__ B, float* __restrict__ C,
    int M, int N, int K, int lda, int ldb, int ldc, int nb, int mb)
{
    using St = Stage<TATR, TBTR>;
    int tid = threadIdx.x;
    int w = tid >> 5, lane = tid & 31;
    int wm = w >> 1, wn = w & 1;
    int g = lane >> 2, tig = lane & 3;

    float acc[2][8][4];
#pragma unroll
    for (int mi = 0; mi < 2; ++mi)
#pragma unroll
        for (int ni = 0; ni < 8; ++ni)
#pragma unroll
            for (int e = 0; e < 4; ++e) acc[mi][ni][e] = 0.f;

    float4 pa0 = St::fetchA(A, lda, M, K, mb, 0, tid, 0);
    float4 pa1 = St::fetchA(A, lda, M, K, mb, 0, tid, 1);
    float4 pb0 = St::fetchB2(B, ldb, N, K, nb, 0, tid, 0);
    float4 pb1 = St::fetchB2(B, ldb, N, K, nb, 0, tid, 1);
    St::storeA(As, 0, pa0, tid, 0); St::storeA(As, 0, pa1, tid, 1);
    St::storeB2(Bs, 0, pb0, tid, 0); St::storeB2(Bs, 0, pb1, tid, 1);
    __syncthreads();

    int nchunks = (K + 15) / 16;
    for (int ch = 0; ch < nchunks; ++ch) {
        int cur = ch & 1, nxt = cur ^ 1;
        bool more = (ch + 1) < nchunks;
        if (more) {
            int kbn = (ch + 1) * 16;
            pa0 = St::fetchA(A, lda, M, K, mb, kbn, tid, 0);
            pa1 = St::fetchA(A, lda, M, K, mb, kbn, tid, 1);
            pb0 = St::fetchB2(B, ldb, N, K, nb, kbn, tid, 0);
            pb1 = St::fetchB2(B, ldb, N, K, nb, kbn, tid, 1);
        }
#pragma unroll
        for (int ksv = 0; ksv < 16; ksv += 8) {
            uint32_t af[2][4];
#pragma unroll
            for (int mi = 0; mi < 2; ++mi) {
                int mrow = wm * 32 + mi * 16 + g;
                CVT_TF32(af[mi][0], As[cur][ksv + tig][mrow]);
                CVT_TF32(af[mi][1], As[cur][ksv + tig][mrow + 8]);
                CVT_TF32(af[mi][2], As[cur][ksv + tig + 4][mrow]);
                CVT_TF32(af[mi][3], As[cur][ksv + tig + 4][mrow + 8]);
            }
#pragma unroll
            for (int ni = 0; ni < 8; ++ni) {
                int ncol = wn * 64 + ni * 8 + g;
                uint32_t bf[2];
                CVT_TF32(bf[0], Bs[cur][ksv + tig][ncol]);
                CVT_TF32(bf[1], Bs[cur][ksv + tig + 4][ncol]);
                MMA_TF32(acc[0][ni], af[0], bf);
                MMA_TF32(acc[1][ni], af[1], bf);
            }
        }
        if (more) {
            St::storeA(As, nxt, pa0, tid, 0); St::storeA(As, nxt, pa1, tid, 1);
            St::storeB2(Bs, nxt, pb0, tid, 0); St::storeB2(Bs, nxt, pb1, tid, 1);
        }
        __syncthreads();
    }

#pragma unroll
    for (int mi = 0; mi < 2; ++mi) {
        int row0 = mb + wm * 32 + mi * 16 + g;
#pragma unroll
        for (int ni = 0; ni < 8; ++ni) {
            int col0 = nb + wn * 64 + ni * 8 + tig * 2;
            if (col0 < N)     C[(size_t)row0 * ldc + col0]           = acc[mi][ni][0];
            if (col0 + 1 < N) C[(size_t)row0 * ldc + col0 + 1]       = acc[mi][ni][1];
            if (col0 < N)     C[(size_t)(row0 + 8) * ldc + col0]     = acc[mi][ni][2];
            if (col0 + 1 < N) C[(size_t)(row0 + 8) * ldc + col0 + 1] = acc[mi][ni][3];
        }
    }
}

// ---------------- all 4 per-phase projection GEMMs in ONE launch (grid.z = s) ------
__global__ void __launch_bounds__(256, 2) gemm_proj(
    int phase,
    const float* __restrict__ in_solv, const float* __restrict__ in_solu,
    const float* __restrict__ solv_Wih, const float* __restrict__ solu_Wih,
    const float* __restrict__ solv_bih, const float* __restrict__ solv_bhh,
    const float* __restrict__ solu_bih, const float* __restrict__ solu_bhh)
{
    __shared__ __align__(16) float As[2][16][132];
    __shared__ __align__(16) float Bs[2][16][68];
    int s = blockIdx.z, model = s >> 1, dir = s & 1;
    const float* X = (phase == 0) ? (model ? in_solu : in_solv) : &d_out1[model][0][0];
    const float* W  = (model ? solu_Wih : solv_Wih) + (size_t)(phase * 2 + dir) * GAT * DIN;
    const float* B1 = (model ? solu_bih : solv_bih) + (size_t)(phase * 2 + dir) * GAT;
    const float* B2 = (model ? solu_bhh : solv_bhh) + (size_t)(phase * 2 + dir) * GAT;
    gemm128_body<0, 1, true>(As, Bs, X, W, &d_xg[s][0][0], B1, B2,
                             TT, GAT, DIN, DIN, DIN, GAT,
                             blockIdx.x * 64, blockIdx.y * 128);
}

// ---------------- S = H @ G^T (tf32, 128x128 tiles) --------------------------------
__global__ void __launch_bounds__(256, 2) gemm_s_tf32(
    const float* __restrict__ H, const float* __restrict__ G, float* __restrict__ S)
{
    __shared__ __align__(16) float As[2][16][132];
    __shared__ __align__(16) float Bs[2][16][132];
    gemm_tf32_wide<0, 1>(As, Bs, H, G, S, TT, TT, 300, 300, 300, TT,
                         blockIdx.x * 128, blockIdx.y * 128);
}

// ---------------- split-K P/Q partials (tf32 128x128), grid.z = (chunk<<1)|pq ------
__global__ void __launch_bounds__(256, 2) gemm_pq_split(
    const float* __restrict__ S, const float* __restrict__ G, const float* __restrict__ H)
{
    __shared__ __align__(16) float As[2][16][132];
    __shared__ __align__(16) float Bs[2][16][132];
    int pq = blockIdx.z & 1, c = blockIdx.z >> 1;
    float* Cout = &d_PQp[pq][c][0];
    if (pq == 0) {
        gemm_tf32_wide<0, 0>(As, Bs, S + (size_t)c * 1024,
                             G + (size_t)c * 1024 * 300, Cout,
                             TT, 300, 1024, TT, 300, 300,
                             blockIdx.x * 128, blockIdx.y * 128);
    } else {
        gemm_tf32_wide<1, 0>(As, Bs, S + (size_t)c * 1024 * TT,
                             H + (size_t)c * 1024 * 300, Cout,
                             TT, 300, 1024, TT, 300, 300,
                             blockIdx.x * 128, blockIdx.y * 128);
    }
}

// ---------------- row softmax of d_S in place (shfl reductions) --------------------
__global__ void __launch_bounds__(256) softmax_rows()
{
    int row = blockIdx.x;
    float* r = &d_S[row][0];
    int tid = threadIdx.x;
    int lane = tid & 31, wid = tid >> 5;
    __shared__ float red[8];
    __shared__ float bc;

    float v[16];
#pragma unroll
    for (int i = 0; i < 16; i++) v[i] = r[tid + i * 256];

    float m = -1e30f;
#pragma unroll
    for (int i = 0; i < 16; i++) m = fmaxf(m, v[i]);
#pragma unroll
    for (int o = 16; o; o >>= 1) m = fmaxf(m, __shfl_xor_sync(0xffffffffu, m, o));
    if (lane == 0) red[wid] = m;
    __syncthreads();
    if (tid == 0) {
        float mm = red[0];
#pragma unroll
        for (int i = 1; i < 8; i++) mm = fmaxf(mm, red[i]);
        bc = mm;
    }
    __syncthreads();
    m = bc;

    float ssum = 0.f;
#pragma unroll
    for (int i = 0; i < 16; i++) { v[i] = __expf(v[i] - m); ssum += v[i]; }
#pragma unroll
    for (int o = 16; o; o >>= 1) ssum += __shfl_xor_sync(0xffffffffu, ssum, o);
    if (lane == 0) red[wid] = ssum;
    __syncthreads();
    if (tid == 0) {
        float ss = red[0];
#pragma unroll
        for (int i = 1; i < 8; i++) ss += red[i];
        bc = 1.f / ss;
    }
    __syncthreads();
    float inv = bc;

#pragma unroll
    for (int i = 0; i < 16; i++) r[tid + i * 256] = v[i] * inv;
}

// ---------------- u/v sums (reads split-K partials directly, coalesced) ------------
__global__ void __launch_bounds__(256) uvsum_part()
{
    int b = blockIdx.x, tid = threadIdx.x;
    const float* H  = &d_HG[0][0][0];
    const float* G  = &d_HG[1][0][0];
    const float* P0 = &d_PQp[0][0][0], *P1 = &d_PQp[0][1][0];
    const float* P2 = &d_PQp[0][2][0], *P3 = &d_PQp[0][3][0];
    const float* Q0 = &d_PQp[1][0][0], *Q1 = &d_PQp[1][1][0];
    const float* Q2 = &d_PQp[1][2][0], *Q3 = &d_PQp[1][3][0];

    float a0 = 0.f, a1 = 0.f, a2 = 0.f;
    for (int i = b * 64; i < b * 64 + 64; ++i) {
        size_t base = (size_t)i * 300;
        {
            size_t o = base + tid;
            float p = (P0[o] + P1[o]) + (P2[o] + P3[o]);
            a0 += fmaxf(H[o], p);
        }
        {
            int d = tid + 256;
            if (d < 300) {
                size_t o = base + d;
                float p = (P0[o] + P1[o]) + (P2[o] + P3[o]);
                a1 += fmaxf(H[o], p);
            } else {
                size_t o = base + (d - 300);
                float q = (Q0[o] + Q1[o]) + (Q2[o] + Q3[o]);
                a1 += fmaxf(G[o], q);
            }
        }
        if (tid < 88) {
            size_t o = base + tid + 212;
            float q = (Q0[o] + Q1[o]) + (Q2[o] + Q3[o]);
            a2 += fmaxf(G[o], q);
        }
    }
    d_uvp[b][tid] = a0;
    d_uvp[b][tid + 256] = a1;
    if (tid < 88) d_uvp[b][tid + 512] = a2;
}

__global__ void __launch_bounds__(256) uvsum_final()
{
    int d = blockIdx.x * 256 + threadIdx.x;
    if (d >= 600) return;
    float s = 0.f;
#pragma unroll
    for (int b = 0; b < 64; ++b) s += d_uvp[b][d];
    d_inp[d] = s;
}

// ---------------- FC head ----------------------------------------------------------
__global__ void fc1_kernel(const float* __restrict__ w, const float* __restrict__ b)
{
    __shared__ float inp[600];
    int tid = threadIdx.x;
    for (int k = tid; k < 600; k += 128) inp[k] = d_inp[k];
    __syncthreads();
    int o = blockIdx.x * 128 + tid;
    if (o < 2000) {
        const float* wr = w + (size_t)o * 600;
        float s = b[o];
        for (int k = 0; k < 600; k++) s += wr[k] * inp[k];
        d_hid[o] = fmaxf(s, 0.f);
    }
}

__global__ void fc2_kernel(const float* __restrict__ w, const float* __restrict__ b,
                           float* __restrict__ out)
{
    int tid = threadIdx.x;
    float s = 0.f;
    for (int k = tid; k < 2000; k += 256) s += d_hid[k] * w[k];
    __shared__ float red[256];
    red[tid] = s; __syncthreads();
    for (int st = 128; st; st >>= 1) { if (tid < st) red[tid] += red[tid + st]; __syncthreads(); }
    if (tid == 0) out[0] = red[0] + b[0];
}

// ---------------- launch orchestration ---------------------------------------------
extern "C" void kernel_launch(void* const* d_in, const int* in_sizes, int n_in,
                              void* d_out, int out_size)
{
    const float* in_solv  = (const float*)d_in[0];
    const float* in_solu  = (const float*)d_in[1];
    const float* solv_Wih = (const float*)d_in[2];
    const float* solv_Whh = (const float*)d_in[3];
    const float* solv_bih = (const float*)d_in[4];
    const float* solv_bhh = (const float*)d_in[5];
    const float* solu_Wih = (const float*)d_in[6];
    const float* solu_Whh = (const float*)d_in[7];
    const float* solu_bih = (const float*)d_in[8];
    const float* solu_bhh = (const float*)d_in[9];
    const float* fc1_w    = (const float*)d_in[10];
    const float* fc1_b    = (const float*)d_in[11];
    const float* fc2_w    = (const float*)d_in[12];
    const float* fc2_b    = (const float*)d_in[13];

    float *p_HG, *p_S;
    cudaGetSymbolAddress((void**)&p_HG, d_HG);
    cudaGetSymbolAddress((void**)&p_S,  d_S);

    pack_whh<<<(8 * 8 * 640 * 5 + 255) / 256, 256>>>(solv_Whh, solu_Whh);

    for (int phase = 0; phase < 2; ++phase) {
        gemm_proj<<<dim3(10, 32, 4), 256>>>(phase, in_solv, in_solu,
                                            solv_Wih, solu_Wih,
                                            solv_bih, solv_bhh, solu_bih, solu_bhh);
        cudaLaunchConfig_t cfg = {};
        cfg.gridDim = dim3(32, 1, 1);
        cfg.blockDim = dim3(640, 1, 1);
        cfg.dynamicSmemBytes = 0;
        cfg.stream = 0;
        cudaLaunchAttribute attrs[1];
        attrs[0].id = cudaLaunchAttributeClusterDimension;
        attrs[0].val.clusterDim = {8, 1, 1};
        cfg.attrs = attrs;
        cfg.numAttrs = 1;
        cudaLaunchKernelEx(&cfg, lstm_rec_cl, phase);
    }

    const float* H = p_HG;
    const float* G = p_HG + (size_t)TT * 300;

    gemm_s_tf32<<<dim3(32, 32), 256>>>(H, G, p_S);
    softmax_rows<<<TT, 256>>>();
    gemm_pq_split<<<dim3(3, 32, 8), 256>>>(p_S, G, H);
    uvsum_part<<<64, 256>>>();
    uvsum_final<<<3, 256>>>();
    fc1_kernel<<<(2000 + 127) / 128, 128>>>(fc1_w, fc1_b);
    fc2_kernel<<<1, 256>>>(fc2_w, fc2_b, (float*)d_out);
}